// round 6
// baseline (speedup 1.0000x reference)
#include <cuda_runtime.h>
#include <stdint.h>

#define Bn 64
#define Cn 2
#define Nn 16
#define NBINS 256
#define VOX 262144
#define NBC 128

#define THREADS 256
#define BCG 32                 // bc rows per block (lane <-> bc)
#define NBCG 4
#define CHUNK 2048             // voxels per block = 32 j-lines
#define NCHUNK 128             // VOX / CHUNK
#define VOXT 256               // voxels per tile step (8 half-lines)
#define STEPS 8                // CHUNK / VOXT
#define XSTRIDE 258            // floats per bc row in xs (8B-aligned, 2-way bank conflict)
#define CBINS 25               // ax,az in 0..4 -> compact bin = ax*5+az
#define HSTRIDE 33             // hist row stride -> bank (lane+cb)%32, conflict-free
#define MAXSEG 12

#define XSBUF_F (BCG*XSTRIDE)          // 8256 floats / buffer
#define HIST_F  (8*BCG*HSTRIDE)        // 8448 floats
#define NHALF   (CHUNK/32)             // 64 half-lines / chunk
#define SMEM_BYTES (2*XSBUF_F*4 + HIST_F*4 + NHALF*4 + NHALF*MAXSEG)

__device__ float g_scratch[NBC * NBINS];   // zero at load; norm re-zeroes each launch

__device__ __forceinline__ void stage(const float* __restrict__ x, int bc0, int v0,
                                      float* dst, int tid) {
    #pragma unroll
    for (int i = 0; i < 16; i++) {
        int lin = tid + i * THREADS;       // 0..4095 : 8B units
        int row = lin >> 7;                // 32 rows x 128 units
        int u   = lin & 127;
        const float* g = x + (size_t)(bc0 + row) * VOX + v0 + u * 2;
        unsigned s = (unsigned)__cvta_generic_to_shared(dst + row * XSTRIDE + u * 2);
        asm volatile("cp.async.ca.shared.global [%0], [%1], 8;\n" :: "r"(s), "l"(g));
    }
}

// One warp processes one half-line (32 k) for 32 bc rows (lane = bc).
// mask/segbins are warp-uniform; deposits are conflict-free non-atomic SMEM RMW.
template<int K0>
__device__ __forceinline__ void process_half(const float* __restrict__ xrow,
                                             float c0, unsigned mask,
                                             const unsigned char* __restrict__ sb,
                                             float* __restrict__ hrow) {
    float run = 0.f;
    #pragma unroll
    for (int k = 0; k < 32; k++) {
        if (k > 0 && ((mask >> k) & 1u)) {          // warp-uniform branch
            int cb = sb[__popc(mask & ((1u << k) - 1u))];
            hrow[cb] += run;                        // LDS+FADD+STS, lane-distinct rows
            run = 0.f;
        }
        float fk = (float)(K0 + k);                 // compile-time literal
        float m = sqrtf(fmaf(fk, fk, c0));
        run = fmaf(xrow[k], m, run);
    }
    hrow[sb[__popc(mask)]] += run;
}

__global__ void __launch_bounds__(THREADS) accum_kernel(const float* __restrict__ x) {
    extern __shared__ float sm[];
    float* xs   = sm;                                  // 2 * XSBUF_F
    float* hist = sm + 2 * XSBUF_F;                    // HIST_F
    unsigned* masks = (unsigned*)(hist + HIST_F);      // NHALF
    unsigned char* segb = (unsigned char*)(masks + NHALF);

    const int tid  = threadIdx.x;
    const int w    = tid >> 5, lane = tid & 31;
    const int chunk0 = blockIdx.x * CHUNK;
    const int bc0    = blockIdx.y * BCG;

    // Prefetch tile 0 while we compute bin geometry.
    stage(x, bc0, chunk0, xs, tid);
    asm volatile("cp.async.commit_group;\n" ::: "memory");

    // Bin geometry (per-chunk, bc-independent). binb temporarily lives in hist.
    unsigned char* binb = (unsigned char*)hist;
    #pragma unroll
    for (int i2 = 0; i2 < CHUNK / THREADS; i2++) {
        int lv = tid + i2 * THREADS;
        int v = chunk0 + lv;
        float fi = (float)(v >> 12);
        float fj = (float)((v >> 6) & 63);
        float fk = (float)(v & 63);
        float xc = sqrtf(fj * fj + fk * fk);
        float zc = sqrtf(fj * fj + fi * fi);
        const float DEG = 57.29577951308232f;   // 180/pi
        int ax = (int)floorf(atan2f(xc, fi) * DEG / 22.0f);
        int az = (int)floorf(atan2f(fk, zc) * DEG / 22.0f);
        binb[lv] = (unsigned char)(ax * 5 + az);
    }
    __syncthreads();

    // Build per-half-line boundary mask + segment-bin list.
    if (tid < NHALF) {
        int base = tid * 32;
        unsigned mask = 0;
        unsigned char prev = binb[base];
        unsigned char* s = segb + tid * MAXSEG;
        s[0] = prev;
        int ns = 1;
        for (int k = 1; k < 32; k++) {
            unsigned char b = binb[base + k];
            if (b != prev) { mask |= 1u << k; s[ns++] = b; prev = b; }
        }
        masks[tid] = mask;
    }
    __syncthreads();
    for (int i2 = tid; i2 < HIST_F; i2 += THREADS) hist[i2] = 0.f;   // binb dead now
    __syncthreads();

    float* hrow = hist + (w * BCG + lane) * HSTRIDE;

    #pragma unroll 1
    for (int s = 0; s < STEPS; s++) {
        if (s + 1 < STEPS) {
            stage(x, bc0, chunk0 + (s + 1) * VOXT, xs + ((s + 1) & 1) * XSBUF_F, tid);
            asm volatile("cp.async.commit_group;\n" ::: "memory");
            asm volatile("cp.async.wait_group 1;\n" ::: "memory");
        } else {
            asm volatile("cp.async.wait_group 0;\n" ::: "memory");
        }
        __syncthreads();

        const int h = s * 8 + w;                 // half-line index in chunk
        const int v0 = chunk0 + h * 32;
        const float fi = (float)(v0 >> 12);
        const float fj = (float)((v0 >> 6) & 63);
        const float c0 = fi * fi + fj * fj;
        const float* xrow = xs + (s & 1) * XSBUF_F + lane * XSTRIDE + w * 32;
        const unsigned mask = masks[h];
        const unsigned char* sb = segb + h * MAXSEG;

        if (w & 1) process_half<32>(xrow, c0, mask, sb, hrow);
        else       process_half<0 >(xrow, c0, mask, sb, hrow);
        __syncthreads();
    }

    // Reduce the 8 per-warp histograms and flush to global (25 live bins x 32 bc).
    for (int idx = tid; idx < BCG * CBINS; idx += THREADS) {
        int bcl = idx / CBINS;
        int cb  = idx - bcl * CBINS;
        float s = 0.f;
        #pragma unroll
        for (int w2 = 0; w2 < 8; w2++) s += hist[(w2 * BCG + bcl) * HSTRIDE + cb];
        int ax = cb / 5;
        int bin = ax * Nn + (cb - ax * 5);
        if (s != 0.f) atomicAdd(&g_scratch[(bc0 + bcl) * NBINS + bin], s);
    }
}

// Per-channel norm over (B,N,N)=16384 values: fp32 two-pass + shuffle reduction.
__global__ void norm_kernel(const float* __restrict__ gamma,
                            const float* __restrict__ beta,
                            float* __restrict__ out) {
    const int c = blockIdx.x, tid = threadIdx.x;
    const int M = Bn * NBINS;
    __shared__ float red[8];
    __shared__ float sh_mean, sh_scale, sh_shift;

    float s = 0.f;
    for (int idx = tid; idx < M; idx += THREADS) {
        int b = idx >> 8, n = idx & 255;
        s += g_scratch[(b * Cn + c) * NBINS + n];
    }
    #pragma unroll
    for (int o = 16; o; o >>= 1) s += __shfl_down_sync(0xffffffffu, s, o);
    if ((tid & 31) == 0) red[tid >> 5] = s;
    __syncthreads();
    if (tid == 0) {
        float t = 0.f;
        #pragma unroll
        for (int i = 0; i < 8; i++) t += red[i];
        sh_mean = t / (float)M;
    }
    __syncthreads();
    const float mean = sh_mean;

    float s2 = 0.f;
    for (int idx = tid; idx < M; idx += THREADS) {
        int b = idx >> 8, n = idx & 255;
        float d = g_scratch[(b * Cn + c) * NBINS + n] - mean;
        s2 += d * d;
    }
    __syncthreads();
    #pragma unroll
    for (int o = 16; o; o >>= 1) s2 += __shfl_down_sync(0xffffffffu, s2, o);
    if ((tid & 31) == 0) red[tid >> 5] = s2;
    __syncthreads();
    if (tid == 0) {
        float t = 0.f;
        #pragma unroll
        for (int i = 0; i < 8; i++) t += red[i];
        float var = t / (float)M;
        float sc = rsqrtf(var + 1e-5f) * gamma[c];
        sh_scale = sc;
        sh_shift = beta[c] - mean * sc;
    }
    __syncthreads();
    const float scale = sh_scale, shift = sh_shift;
    for (int idx = tid; idx < M; idx += THREADS) {
        int b = idx >> 8, n = idx & 255;
        int off = (b * Cn + c) * NBINS + n;
        out[off] = g_scratch[off] * scale + shift;
        g_scratch[off] = 0.f;   // restore zero-invariant for next graph replay
    }
}

extern "C" void kernel_launch(void* const* d_in, const int* in_sizes, int n_in,
                              void* d_out, int out_size) {
    const float* x     = (const float*)d_in[0];
    const float* gamma = (const float*)d_in[1];
    const float* beta  = (const float*)d_in[2];
    float* out = (float*)d_out;

    cudaFuncSetAttribute(accum_kernel,
                         cudaFuncAttributeMaxDynamicSharedMemorySize, SMEM_BYTES);
    dim3 grid(NCHUNK, NBCG);
    accum_kernel<<<grid, THREADS, SMEM_BYTES>>>(x);
    norm_kernel<<<Cn, THREADS>>>(gamma, beta, out);
}

// round 7
// speedup vs baseline: 1.2483x; 1.2483x over previous
#include <cuda_runtime.h>
#include <stdint.h>

#define Bn 64
#define Cn 2
#define Nn 16
#define NBINS 256
#define VOX 262144
#define NBC 128

#define THREADS 256
#define BCG 32                 // bc rows per block (lane <-> bc)
#define NBCG 4
#define CHUNK 2048             // voxels per block = 32 j-lines
#define NCHUNK 128             // VOX / CHUNK
#define VOXT 256               // voxels per tile step (8 half-lines)
#define STEPS 8                // CHUNK / VOXT
#define XSTRIDE 258            // floats per bc row in xs
#define CBINS 25               // ax,az in 0..4 -> compact bin = ax*5+az
#define HSTRIDE 33             // hist row stride, conflict-free deposits
#define MAXSEG 12
#define NHALF_TOT (VOX/32)     // 8192 half-lines total
#define NHALF 64               // half-lines per chunk

#define XSBUF_F (BCG*XSTRIDE)          // 8256 floats / buffer
#define HIST_F  (8*BCG*HSTRIDE)        // 8448 floats
// xs(2) + hist + masks(64 u32) + segb(768 B) + mags(2048 f)
#define SMEM_BYTES (2*XSBUF_F*4 + HIST_F*4 + NHALF*4 + NHALF*MAXSEG + CHUNK*4)

__device__ float  g_scratch[NBC * NBINS];   // zero at load; apply re-zeroes
__device__ double g_stats[2 * Cn];          // zero at load; finalize re-zeroes
__device__ float  g_coef[2 * Cn];
__device__ unsigned      g_masks[NHALF_TOT];
__device__ unsigned char g_segb[NHALF_TOT * MAXSEG];
__device__ float         g_mag[VOX];

// One-time geometry: per-voxel bin via atan2 (computed ONCE per launch),
// half-line boundary masks via ballot, segment-bin lists, mag table.
__global__ void __launch_bounds__(THREADS) table_kernel() {
    int v = blockIdx.x * THREADS + threadIdx.x;
    int lane = threadIdx.x & 31;
    float fi = (float)(v >> 12);
    float fj = (float)((v >> 6) & 63);
    float fk = (float)(v & 63);
    g_mag[v] = sqrtf(fi * fi + fj * fj + fk * fk);
    float xc = sqrtf(fj * fj + fk * fk);
    float zc = sqrtf(fj * fj + fi * fi);
    const float DEG = 57.29577951308232f;   // 180/pi
    int ax = (int)floorf(atan2f(xc, fi) * DEG / 22.0f);
    int az = (int)floorf(atan2f(fk, zc) * DEG / 22.0f);
    int cb = ax * 5 + az;                    // compact bin

    int prev = __shfl_up_sync(0xffffffffu, cb, 1);
    bool bnd = (lane > 0) && (cb != prev);
    unsigned mask = __ballot_sync(0xffffffffu, bnd);
    int h = v >> 5;
    if (lane == 0) {
        g_masks[h] = mask;
        g_segb[h * MAXSEG] = (unsigned char)cb;
    }
    if (bnd)
        g_segb[h * MAXSEG + __popc(mask & ((1u << lane) - 1u)) + 1] = (unsigned char)cb;
}

__device__ __forceinline__ void stage(const float* __restrict__ x, int bc0, int v0,
                                      float* dst, int tid) {
    #pragma unroll
    for (int i = 0; i < 16; i++) {
        int lin = tid + i * THREADS;       // 0..4095 : 8B units
        int row = lin >> 7;                // 32 rows x 128 units
        int u   = lin & 127;
        const float* g = x + (size_t)(bc0 + row) * VOX + v0 + u * 2;
        unsigned s = (unsigned)__cvta_generic_to_shared(dst + row * XSTRIDE + u * 2);
        asm volatile("cp.async.ca.shared.global [%0], [%1], 8;\n" :: "r"(s), "l"(g));
    }
}

// One warp: one half-line (32 k) for 32 bc rows (lane = bc). mask/segbins are
// warp-uniform; mag is a smem broadcast; deposits are conflict-free SMEM RMW.
__device__ __forceinline__ void process_half(const float* __restrict__ xrow,
                                             const float* __restrict__ magrow,
                                             unsigned mask,
                                             const unsigned char* __restrict__ sb,
                                             float* __restrict__ hrow) {
    float run = 0.f;
    #pragma unroll
    for (int k = 0; k < 32; k++) {
        if (k > 0 && ((mask >> k) & 1u)) {          // warp-uniform branch
            int cb = sb[__popc(mask & ((1u << k) - 1u))];
            hrow[cb] += run;
            run = 0.f;
        }
        run = fmaf(xrow[k], magrow[k], run);
    }
    hrow[sb[__popc(mask)]] += run;
}

__global__ void __launch_bounds__(THREADS) accum_kernel(const float* __restrict__ x) {
    extern __shared__ float sm[];
    float* xs   = sm;                                  // 2 * XSBUF_F
    float* hist = sm + 2 * XSBUF_F;                    // HIST_F
    unsigned* masks = (unsigned*)(hist + HIST_F);      // NHALF
    unsigned char* segb = (unsigned char*)(masks + NHALF);  // NHALF*MAXSEG
    float* mags = (float*)(segb + NHALF * MAXSEG);     // CHUNK

    const int tid  = threadIdx.x;
    const int w    = tid >> 5, lane = tid & 31;
    const int chunk0 = blockIdx.x * CHUNK;
    const int bc0    = blockIdx.y * BCG;

    // Prefetch tile 0, then pull precomputed tables (tiny, L2-resident).
    stage(x, bc0, chunk0, xs, tid);
    asm volatile("cp.async.commit_group;\n" ::: "memory");

    const int h0 = blockIdx.x * NHALF;
    if (tid < NHALF) masks[tid] = g_masks[h0 + tid];
    // segb: 768 bytes, 4-aligned (h0*MAXSEG is a multiple of 768)
    if (tid < NHALF * MAXSEG / 4)
        ((unsigned*)segb)[tid] = ((const unsigned*)(g_segb + (size_t)h0 * MAXSEG))[tid];
    #pragma unroll
    for (int i = 0; i < CHUNK / THREADS; i++)
        mags[tid + i * THREADS] = g_mag[chunk0 + tid + i * THREADS];
    for (int i = tid; i < HIST_F; i += THREADS) hist[i] = 0.f;
    __syncthreads();

    float* hrow = hist + (w * BCG + lane) * HSTRIDE;

    #pragma unroll 1
    for (int s = 0; s < STEPS; s++) {
        if (s + 1 < STEPS) {
            stage(x, bc0, chunk0 + (s + 1) * VOXT, xs + ((s + 1) & 1) * XSBUF_F, tid);
            asm volatile("cp.async.commit_group;\n" ::: "memory");
            asm volatile("cp.async.wait_group 1;\n" ::: "memory");
        } else {
            asm volatile("cp.async.wait_group 0;\n" ::: "memory");
        }
        __syncthreads();

        const int h = s * 8 + w;                 // half-line index in chunk
        const float* xrow   = xs + (s & 1) * XSBUF_F + lane * XSTRIDE + w * 32;
        const float* magrow = mags + h * 32;
        process_half(xrow, magrow, masks[h], segb + h * MAXSEG, hrow);
        __syncthreads();
    }

    // Reduce 8 per-warp histograms, flush live bins to global.
    for (int idx = tid; idx < BCG * CBINS; idx += THREADS) {
        int bcl = idx / CBINS;
        int cb  = idx - bcl * CBINS;
        float s = 0.f;
        #pragma unroll
        for (int w2 = 0; w2 < 8; w2++) s += hist[(w2 * BCG + bcl) * HSTRIDE + cb];
        int ax = cb / 5;
        int bin = ax * Nn + (cb - ax * 5);
        if (s != 0.f) atomicAdd(&g_scratch[(bc0 + bcl) * NBINS + bin], s);
    }
}

// Norm stage 1: partial sums per channel (fp64, double atomics into g_stats).
__global__ void stats_kernel() {
    const int c = blockIdx.x, slice = blockIdx.y, tid = threadIdx.x;
    __shared__ double red[2][8];
    int idx = slice * 1024 + tid;
    // each block covers 1024 of the 16384 (b,n) pairs, 4 per thread
    double s = 0.0, s2 = 0.0;
    #pragma unroll
    for (int i = 0; i < 4; i++) {
        int id2 = idx + i * 256;
        int b = id2 >> 8, n = id2 & 255;
        double v = (double)g_scratch[(b * Cn + c) * NBINS + n];
        s += v; s2 += v * v;
    }
    #pragma unroll
    for (int o = 16; o; o >>= 1) {
        s  += __shfl_down_sync(0xffffffffu, s,  o);
        s2 += __shfl_down_sync(0xffffffffu, s2, o);
    }
    if ((tid & 31) == 0) { red[0][tid >> 5] = s; red[1][tid >> 5] = s2; }
    __syncthreads();
    if (tid == 0) {
        double t = 0.0, t2 = 0.0;
        #pragma unroll
        for (int i = 0; i < 8; i++) { t += red[0][i]; t2 += red[1][i]; }
        atomicAdd(&g_stats[2 * c], t);
        atomicAdd(&g_stats[2 * c + 1], t2);
    }
}

// Norm stage 2: coefficients; re-zero g_stats for next replay.
__global__ void finalize_kernel(const float* __restrict__ gamma,
                                const float* __restrict__ beta) {
    int c = threadIdx.x;
    if (c < Cn) {
        const double M = (double)(Bn * NBINS);
        double mean = g_stats[2 * c] / M;
        double var  = g_stats[2 * c + 1] / M - mean * mean;
        double rs   = 1.0 / sqrt(var + 1e-5);
        float scale = (float)rs * gamma[c];
        g_coef[2 * c]     = scale;
        g_coef[2 * c + 1] = beta[c] - (float)mean * scale;
        g_stats[2 * c] = 0.0;
        g_stats[2 * c + 1] = 0.0;
    }
}

// Norm stage 3: apply affine, write out, re-zero g_scratch.
__global__ void apply_kernel(float* __restrict__ out) {
    int idx = blockIdx.x * blockDim.x + threadIdx.x;   // 0..32767
    int c = (idx >> 8) & (Cn - 1);
    out[idx] = g_scratch[idx] * g_coef[2 * c] + g_coef[2 * c + 1];
    g_scratch[idx] = 0.f;
}

extern "C" void kernel_launch(void* const* d_in, const int* in_sizes, int n_in,
                              void* d_out, int out_size) {
    const float* x     = (const float*)d_in[0];
    const float* gamma = (const float*)d_in[1];
    const float* beta  = (const float*)d_in[2];
    float* out = (float*)d_out;

    cudaFuncSetAttribute(accum_kernel,
                         cudaFuncAttributeMaxDynamicSharedMemorySize, SMEM_BYTES);
    table_kernel<<<VOX / THREADS, THREADS>>>();
    dim3 grid(NCHUNK, NBCG);
    accum_kernel<<<grid, THREADS, SMEM_BYTES>>>(x);
    dim3 sgrid(Cn, 16);
    stats_kernel<<<sgrid, 256>>>();
    finalize_kernel<<<1, 32>>>(gamma, beta);
    apply_kernel<<<NBC * NBINS / 256, 256>>>(out);
}